// round 5
// baseline (speedup 1.0000x reference)
#include <cuda_runtime.h>
#include <cuda_bf16.h>

// Softmax over last 65536 elements of each row; 1024 rows.
// One CTA per row, 1024 threads, float4 vectorized.
// Pass 1: online (max, sum) in a single read. Pass 2: re-read (L2-hit) + write.

#define ROW_LEN      65536
#define NTHREADS     1024
#define V4_PER_ROW   (ROW_LEN / 4)            // 16384
#define V4_PER_THR   (V4_PER_ROW / NTHREADS)  // 16

__global__ __launch_bounds__(NTHREADS)
void softmax_rows_74672301408351(const float* __restrict__ x,
                                 float* __restrict__ out) {
    const size_t base = (size_t)blockIdx.x * ROW_LEN;
    const float4* __restrict__ xv = reinterpret_cast<const float4*>(x + base);
    float4* __restrict__ ov       = reinterpret_cast<float4*>(out + base);
    const int tid = threadIdx.x;

    // ---- Pass 1: online max + sum over this thread's 16 float4s ----
    float m = -3.402823466e38f;
    float s = 0.0f;
#pragma unroll
    for (int i = 0; i < V4_PER_THR; ++i) {
        const float4 v = xv[tid + i * NTHREADS];
        const float lm = fmaxf(fmaxf(v.x, v.y), fmaxf(v.z, v.w));
        const float nm = fmaxf(m, lm);
        s = s * __expf(m - nm)
          + __expf(v.x - nm) + __expf(v.y - nm)
          + __expf(v.z - nm) + __expf(v.w - nm);
        m = nm;
    }

    // ---- Warp reduce (merge (m,s) pairs) ----
#pragma unroll
    for (int off = 16; off > 0; off >>= 1) {
        const float om = __shfl_xor_sync(0xffffffffu, m, off);
        const float os = __shfl_xor_sync(0xffffffffu, s, off);
        const float nm = fmaxf(m, om);
        s = s * __expf(m - nm) + os * __expf(om - nm);
        m = nm;
    }

    // ---- Block reduce across 32 warps ----
    __shared__ float sm[32];
    __shared__ float ss[32];
    const int warp = tid >> 5;
    const int lane = tid & 31;
    if (lane == 0) { sm[warp] = m; ss[warp] = s; }
    __syncthreads();
    if (warp == 0) {
        m = sm[lane];
        s = ss[lane];
#pragma unroll
        for (int off = 16; off > 0; off >>= 1) {
            const float om = __shfl_xor_sync(0xffffffffu, m, off);
            const float os = __shfl_xor_sync(0xffffffffu, s, off);
            const float nm = fmaxf(m, om);
            s = s * __expf(m - nm) + os * __expf(om - nm);
            m = nm;
        }
        if (lane == 0) { sm[0] = m; ss[0] = 1.0f / s; }
    }
    __syncthreads();
    const float M   = sm[0];
    const float inv = ss[0];

    // ---- Pass 2: re-read (should be L2-resident) and write normalized ----
#pragma unroll
    for (int i = 0; i < V4_PER_THR; ++i) {
        const float4 v = xv[tid + i * NTHREADS];
        float4 o;
        o.x = __expf(v.x - M) * inv;
        o.y = __expf(v.y - M) * inv;
        o.z = __expf(v.z - M) * inv;
        o.w = __expf(v.w - M) * inv;
        ov[tid + i * NTHREADS] = o;
    }
}

extern "C" void kernel_launch(void* const* d_in, const int* in_sizes, int n_in,
                              void* d_out, int out_size) {
    const float* x = (const float*)d_in[0];
    float* out = (float*)d_out;
    const int rows = in_sizes[0] / ROW_LEN;  // 16*64 = 1024
    softmax_rows_74672301408351<<<rows, NTHREADS>>>(x, out);
}